// round 6
// baseline (speedup 1.0000x reference)
#include <cuda_runtime.h>
#include <cuda_bf16.h>
#include <cstdint>

#define N_NODES 100000
#define N_EDGES 1000000
#define D 64
#define ALPHA 10.0f
#define NBLK_SCAN 391    // ceil(100000/256)
#define GTILES 1563      // ceil(100000/64)

// ---------------- scratch (device globals) ----------------
__device__ int   g_cnt[N_NODES];
__device__ int   g_row[N_NODES];
__device__ int   g_cur[N_NODES];
__device__ int   g_bsum[512];
__device__ int   g_perm[N_EDGES];          // src ids, sorted by dst
__device__ float g_deg[N_NODES];
__device__ float g_norm[N_NODES];
__device__ float g_hs0[N_NODES * D];       // norm * feats          (gather1 input)
__device__ float g_S1n[N_NODES * D];       // norm   * S1           (gemm m=1 input)
__device__ float g_hs1[N_NODES * D];       // norm^2 * S1           (gather2 input)
__device__ float g_S2n[N_NODES * D];       // norm   * S2           (gemm m=2 input)

// ---------------- zero counts + deg ----------------
__global__ void zero_kernel() {
    int i = blockIdx.x * blockDim.x + threadIdx.x;   // < 50000
    if (i < 25000) {
        ((int4*)g_cnt)[i] = make_int4(0, 0, 0, 0);
    } else if (i < 50000) {
        ((float4*)g_deg)[i - 25000] = make_float4(0.f, 0.f, 0.f, 0.f);
    }
}

// ---------------- histogram + weighted degree ----------------
__global__ void hist_kernel(const int* __restrict__ dst,
                            const int* __restrict__ e_feat,
                            const float* __restrict__ edge_weight) {
    int e = blockIdx.x * blockDim.x + threadIdx.x;
    if (e >= N_EDGES) return;
    int d = dst[e];
    atomicAdd(&g_cnt[d], 1);
    float x = edge_weight[e_feat[e] - 1] * ALPHA;
    float w = x > 0.f ? x : 0.01f * x;   // leaky_relu
    atomicAdd(&g_deg[d], w);
}

// ---------------- scan phase A: per-block sums ----------------
__global__ void scanA_kernel() {
    __shared__ int sm[256];
    int i = blockIdx.x * 256 + threadIdx.x;
    int v = (i < N_NODES) ? g_cnt[i] : 0;
    sm[threadIdx.x] = v;
    __syncthreads();
    for (int o = 128; o > 0; o >>= 1) {
        if (threadIdx.x < o) sm[threadIdx.x] += sm[threadIdx.x + o];
        __syncthreads();
    }
    if (threadIdx.x == 0) g_bsum[blockIdx.x] = sm[0];
}

// ---------------- scan phase C: block offset via reduction + intra scan ---
__global__ void scanC_kernel() {
    int tid = threadIdx.x;
    int acc = 0;
    for (int j = tid; j < blockIdx.x; j += 256) acc += g_bsum[j];
    __shared__ int red[256];
    red[tid] = acc;
    __syncthreads();
    for (int o = 128; o > 0; o >>= 1) {
        if (tid < o) red[tid] += red[tid + o];
        __syncthreads();
    }
    int block_off = red[0];
    __syncthreads();

    int i = blockIdx.x * 256 + tid;
    int v = (i < N_NODES) ? g_cnt[i] : 0;
    unsigned lane = tid & 31, wid = tid >> 5;
    int x = v;
    for (int o = 1; o < 32; o <<= 1) {
        int y = __shfl_up_sync(0xffffffffu, x, o);
        if (lane >= o) x += y;
    }
    __shared__ int ws[8];
    if (lane == 31) ws[wid] = x;
    __syncthreads();
    if (wid == 0) {
        int s = (lane < 8) ? ws[lane] : 0;
        for (int o = 1; o < 8; o <<= 1) {
            int y = __shfl_up_sync(0xffffffffu, s, o);
            if (lane >= o) s += y;
        }
        if (lane < 8) ws[lane] = s;
    }
    __syncthreads();
    int excl = x - v + (wid ? ws[wid - 1] : 0) + block_off;
    if (i < N_NODES) {
        g_row[i] = excl;
        g_cur[i] = excl;
    }
}

// ---------------- scatter: build perm (src sorted by dst) ----------------
__global__ void scatter_kernel(const int* __restrict__ src,
                               const int* __restrict__ dst) {
    int e = blockIdx.x * blockDim.x + threadIdx.x;
    if (e >= N_EDGES) return;
    int p = atomicAdd(&g_cur[dst[e]], 1);
    g_perm[p] = src[e];
}

// ---------------- norm + pre-scaled feats ----------------
__global__ void norm_hs0_kernel(const float* __restrict__ feats) {
    int t = blockIdx.x * blockDim.x + threadIdx.x;  // < N_NODES*16
    int n = t >> 4, c = t & 15;
    float nm = rsqrtf(fmaxf(g_deg[n], 1.0f));
    if (c == 0) g_norm[n] = nm;
    float4 v = ((const float4*)feats)[n * 16 + c];
    v.x *= nm; v.y *= nm; v.z *= nm; v.w *= nm;
    ((float4*)g_hs0)[n * 16 + c] = v;
}

// ---------------- gather pass 1 (4-way unrolled) ----------------
__global__ __launch_bounds__(256) void gather1_kernel() {
    int t = blockIdx.x * 256 + threadIdx.x;
    int n = t >> 4, c = t & 15;       // 16 threads per node
    int e = g_row[n];
    int eend = e + g_cnt[n];
    float4 acc = make_float4(0.f, 0.f, 0.f, 0.f);
    const float4* H = (const float4*)g_hs0;
    for (; e + 3 < eend; e += 4) {
        int s0 = g_perm[e], s1 = g_perm[e + 1];
        int s2 = g_perm[e + 2], s3 = g_perm[e + 3];
        float4 a = H[s0 * 16 + c];
        float4 b = H[s1 * 16 + c];
        float4 cc = H[s2 * 16 + c];
        float4 dd = H[s3 * 16 + c];
        acc.x += a.x + b.x + cc.x + dd.x;
        acc.y += a.y + b.y + cc.y + dd.y;
        acc.z += a.z + b.z + cc.z + dd.z;
        acc.w += a.w + b.w + cc.w + dd.w;
    }
    for (; e < eend; e++) {
        int s0 = g_perm[e];
        float4 a = H[s0 * 16 + c];
        acc.x += a.x; acc.y += a.y; acc.z += a.z; acc.w += a.w;
    }
    float nm = g_norm[n];
    float4 v1 = make_float4(acc.x * nm, acc.y * nm, acc.z * nm, acc.w * nm);
    ((float4*)g_S1n)[n * 16 + c] = v1;
    float4 v2 = make_float4(v1.x * nm, v1.y * nm, v1.z * nm, v1.w * nm);
    ((float4*)g_hs1)[n * 16 + c] = v2;
}

// ---------------- gather pass 2 (4-way unrolled) ----------------
__global__ __launch_bounds__(256) void gather2_kernel() {
    int t = blockIdx.x * 256 + threadIdx.x;
    int n = t >> 4, c = t & 15;
    int e = g_row[n];
    int eend = e + g_cnt[n];
    float4 acc = make_float4(0.f, 0.f, 0.f, 0.f);
    const float4* H = (const float4*)g_hs1;
    for (; e + 3 < eend; e += 4) {
        int s0 = g_perm[e], s1 = g_perm[e + 1];
        int s2 = g_perm[e + 2], s3 = g_perm[e + 3];
        float4 a = H[s0 * 16 + c];
        float4 b = H[s1 * 16 + c];
        float4 cc = H[s2 * 16 + c];
        float4 dd = H[s3 * 16 + c];
        acc.x += a.x + b.x + cc.x + dd.x;
        acc.y += a.y + b.y + cc.y + dd.y;
        acc.z += a.z + b.z + cc.z + dd.z;
        acc.w += a.w + b.w + cc.w + dd.w;
    }
    for (; e < eend; e++) {
        int s0 = g_perm[e];
        float4 a = H[s0 * 16 + c];
        acc.x += a.x; acc.y += a.y; acc.z += a.z; acc.w += a.w;
    }
    float nm = g_norm[n];
    ((float4*)g_S2n)[n * 16 + c] =
        make_float4(acc.x * nm, acc.y * nm, acc.z * nm, acc.w * nm);
}

// ================= HMMA (mma.sync) GEMM with bf16 hi/lo split =============
__device__ __forceinline__ void mma16816(float* c, const uint32_t* a,
                                         uint32_t b0, uint32_t b1) {
    asm volatile(
        "mma.sync.aligned.m16n8k16.row.col.f32.bf16.bf16.f32 "
        "{%0,%1,%2,%3}, {%4,%5,%6,%7}, {%8,%9}, {%0,%1,%2,%3};"
        : "+f"(c[0]), "+f"(c[1]), "+f"(c[2]), "+f"(c[3])
        : "r"(a[0]), "r"(a[1]), "r"(a[2]), "r"(a[3]), "r"(b0), "r"(b1));
}

__device__ __forceinline__ uint32_t pack_bf16(float a, float b) {
    __nv_bfloat162 t = __floats2bfloat162_rn(a, b);
    return *reinterpret_cast<uint32_t*>(&t);
}

#define ASTRIDE 33   // words per row (66 bf16)

// m selects the A operand IN DEVICE CODE (device-global symbols are not
// valid host-side pointers — that was the round-5 bug).
__global__ __launch_bounds__(64) void gemm_tc_kernel(
    const float* __restrict__ feats,
    const float* __restrict__ W,
    float* __restrict__ out, int m) {
    __shared__ __align__(16) uint32_t sAhi[64 * ASTRIDE];
    __shared__ __align__(16) uint32_t sAlo[64 * ASTRIDE];
    __shared__ __align__(16) uint32_t sBhi[64 * ASTRIDE];   // Wt[n][k]
    __shared__ __align__(16) uint32_t sBlo[64 * ASTRIDE];

    int tid = threadIdx.x;
    int w = tid >> 5, lane = tid & 31;
    int g = lane >> 2, q = lane & 3;
    int rowbase = blockIdx.x * 64;

    const float* A = (m == 0) ? feats : (m == 1) ? g_S1n : g_S2n;

    // ---- stage A: one row per thread, f32 -> bf16 hi/lo
    {
        int grow = rowbase + tid;
        if (grow < N_NODES) {
            const float4* rp = (const float4*)(A + (size_t)grow * 64);
#pragma unroll
            for (int i = 0; i < 16; i++) {
                float4 v = rp[i];
                float h0 = __bfloat162float(__float2bfloat16_rn(v.x));
                float h1 = __bfloat162float(__float2bfloat16_rn(v.y));
                float h2 = __bfloat162float(__float2bfloat16_rn(v.z));
                float h3 = __bfloat162float(__float2bfloat16_rn(v.w));
                sAhi[tid * ASTRIDE + 2 * i + 0] = pack_bf16(h0, h1);
                sAhi[tid * ASTRIDE + 2 * i + 1] = pack_bf16(h2, h3);
                sAlo[tid * ASTRIDE + 2 * i + 0] = pack_bf16(v.x - h0, v.y - h1);
                sAlo[tid * ASTRIDE + 2 * i + 1] = pack_bf16(v.z - h2, v.w - h3);
            }
        } else {
#pragma unroll
            for (int i = 0; i < 32; i++) {
                sAhi[tid * ASTRIDE + i] = 0;
                sAlo[tid * ASTRIDE + i] = 0;
            }
        }
    }

    // ---- stage B: Wt[n][k] bf16 hi/lo (W is [k][n] row-major f32)
    {
        __nv_bfloat16* bh = (__nv_bfloat16*)sBhi;
        __nv_bfloat16* bl = (__nv_bfloat16*)sBlo;
#pragma unroll
        for (int i = 0; i < 64; i++) {
            int idx = tid + i * 64;          // idx = k*64 + n
            float v = W[idx];
            int k = idx >> 6, n = idx & 63;
            float h = __bfloat162float(__float2bfloat16_rn(v));
            bh[n * 66 + k] = __float2bfloat16_rn(v);
            bl[n * 66 + k] = __float2bfloat16_rn(v - h);
        }
    }
    __syncthreads();

    // ---- MMA mainloop
    float acc[2][8][4];
#pragma unroll
    for (int mt = 0; mt < 2; mt++)
#pragma unroll
        for (int nt = 0; nt < 8; nt++)
#pragma unroll
            for (int i = 0; i < 4; i++) acc[mt][nt][i] = 0.f;

#pragma unroll
    for (int ks = 0; ks < 4; ks++) {
        uint32_t bh[8][2], bl[8][2];
#pragma unroll
        for (int nt = 0; nt < 8; nt++) {
            int n = nt * 8 + g;
            int bw = n * ASTRIDE + q + ks * 8;
            bh[nt][0] = sBhi[bw];     bh[nt][1] = sBhi[bw + 4];
            bl[nt][0] = sBlo[bw];     bl[nt][1] = sBlo[bw + 4];
        }
#pragma unroll
        for (int mt = 0; mt < 2; mt++) {
            int r0 = w * 32 + mt * 16 + g;
            int aw0 = r0 * ASTRIDE + q + ks * 8;
            int aw1 = (r0 + 8) * ASTRIDE + q + ks * 8;
            uint32_t ahi[4] = {sAhi[aw0], sAhi[aw1], sAhi[aw0 + 4], sAhi[aw1 + 4]};
            uint32_t alo[4] = {sAlo[aw0], sAlo[aw1], sAlo[aw0 + 4], sAlo[aw1 + 4]};
#pragma unroll
            for (int nt = 0; nt < 8; nt++) {
                mma16816(acc[mt][nt], ahi, bh[nt][0], bh[nt][1]);
                mma16816(acc[mt][nt], ahi, bl[nt][0], bl[nt][1]);
                mma16816(acc[mt][nt], alo, bh[nt][0], bh[nt][1]);
            }
        }
    }

    // ---- epilogue
#pragma unroll
    for (int mt = 0; mt < 2; mt++) {
        int r0 = rowbase + w * 32 + mt * 16 + g;
#pragma unroll
        for (int nt = 0; nt < 8; nt++) {
            int col = m * 64 + nt * 8 + q * 2;
            if (r0 < N_NODES)
                *(float2*)(out + (size_t)r0 * 192 + col) =
                    make_float2(acc[mt][nt][0], acc[mt][nt][1]);
            if (r0 + 8 < N_NODES)
                *(float2*)(out + (size_t)(r0 + 8) * 192 + col) =
                    make_float2(acc[mt][nt][2], acc[mt][nt][3]);
        }
    }
}

// =================== launch with fork/join overlap ===================
extern "C" void kernel_launch(void* const* d_in, const int* in_sizes, int n_in,
                              void* d_out, int out_size) {
    const float* feats       = (const float*)d_in[0];
    const float* edge_weight = (const float*)d_in[1];
    const float* w0          = (const float*)d_in[2];
    const float* w1          = (const float*)d_in[3];
    const float* w2          = (const float*)d_in[4];
    const int*   src         = (const int*)d_in[5];
    const int*   dst         = (const int*)d_in[6];
    const int*   e_feat      = (const int*)d_in[7];
    float* out = (float*)d_out;

    // Created once on the first (eager, uncaptured) correctness call.
    static cudaStream_t s1 = nullptr, s2 = nullptr;
    static cudaEvent_t eHist, eHs0, eG1, eM0, eM1;
    if (!s1) {
        cudaStreamCreateWithFlags(&s1, cudaStreamNonBlocking);
        cudaStreamCreateWithFlags(&s2, cudaStreamNonBlocking);
        cudaEventCreateWithFlags(&eHist, cudaEventDisableTiming);
        cudaEventCreateWithFlags(&eHs0, cudaEventDisableTiming);
        cudaEventCreateWithFlags(&eG1, cudaEventDisableTiming);
        cudaEventCreateWithFlags(&eM0, cudaEventDisableTiming);
        cudaEventCreateWithFlags(&eM1, cudaEventDisableTiming);
    }

    // --- main: sort pipeline
    zero_kernel<<<(50000 + 255) / 256, 256>>>();
    hist_kernel<<<(N_EDGES + 255) / 256, 256>>>(dst, e_feat, edge_weight);
    cudaEventRecord(eHist, 0);

    // --- s2: gemm m=0 depends only on feats
    cudaStreamWaitEvent(s2, eHist, 0);   // fork point
    gemm_tc_kernel<<<GTILES, 64, 0, s2>>>(feats, w0, out, 0);
    cudaEventRecord(eM0, s2);

    // --- s1: norm+hs0 needs only deg
    cudaStreamWaitEvent(s1, eHist, 0);
    norm_hs0_kernel<<<(N_NODES * 16) / 256, 256, 0, s1>>>(feats);
    cudaEventRecord(eHs0, s1);

    // --- main: continue sort
    scanA_kernel<<<NBLK_SCAN, 256>>>();
    scanC_kernel<<<NBLK_SCAN, 256>>>();
    scatter_kernel<<<(N_EDGES + 255) / 256, 256>>>(src, dst);

    // --- main: gathers (need hs0 + perm)
    cudaStreamWaitEvent(0, eHs0, 0);
    gather1_kernel<<<(N_NODES * 16) / 256, 256>>>();
    cudaEventRecord(eG1, 0);

    // --- s1: gemm m=1 overlaps gather2
    cudaStreamWaitEvent(s1, eG1, 0);
    gemm_tc_kernel<<<GTILES, 64, 0, s1>>>(feats, w1, out, 1);
    cudaEventRecord(eM1, s1);

    // --- main: gather2 + gemm m=2
    gather2_kernel<<<(N_NODES * 16) / 256, 256>>>();
    gemm_tc_kernel<<<GTILES, 64>>>(feats, w2, out, 2);

    // --- join side streams back into main before returning
    cudaStreamWaitEvent(0, eM0, 0);
    cudaStreamWaitEvent(0, eM1, 0);
}

// round 7
// speedup vs baseline: 1.0306x; 1.0306x over previous
#include <cuda_runtime.h>
#include <cuda_bf16.h>
#include <cstdint>

#define N_NODES 100000
#define N_EDGES 1000000
#define D 64
#define ALPHA 10.0f
#define NBLK_SCAN 391    // ceil(100000/256)
#define GTILES 1563      // ceil(100000/64)
#define AGG_FLAG 0x40000000

// ---------------- scratch (device globals) ----------------
__device__ int   g_cnt[N_NODES];
__device__ int   g_row[N_NODES];
__device__ int   g_cur[N_NODES];
__device__ int   g_agg[NBLK_SCAN];         // lookback aggregates (sum | AGG_FLAG)
__device__ int   g_perm[N_EDGES];          // src ids, sorted by dst
__device__ float g_deg[N_NODES];
__device__ float g_norm[N_NODES];
__device__ float g_S1n[N_NODES * D];       // norm * S1   (gemm m=1 input, gather2 src)
__device__ float g_S2n[N_NODES * D];       // norm * S2   (gemm m=2 input)

// ---------------- zero: cnt + deg + agg ----------------
__global__ void zero_kernel() {
    int i = blockIdx.x * blockDim.x + threadIdx.x;
    if (i < 25000) {
        ((int4*)g_cnt)[i] = make_int4(0, 0, 0, 0);
    } else if (i < 50000) {
        ((float4*)g_deg)[i - 25000] = make_float4(0.f, 0.f, 0.f, 0.f);
    } else {
        int j = i - 50000;
        if (j < NBLK_SCAN) g_agg[j] = 0;
    }
}

// ---------------- histogram + weighted degree ----------------
__global__ void hist_kernel(const int* __restrict__ dst,
                            const int* __restrict__ e_feat,
                            const float* __restrict__ edge_weight) {
    int e = blockIdx.x * blockDim.x + threadIdx.x;
    if (e >= N_EDGES) return;
    int d = dst[e];
    atomicAdd(&g_cnt[d], 1);
    float x = edge_weight[e_feat[e] - 1] * ALPHA;
    float w = x > 0.f ? x : 0.01f * x;   // leaky_relu
    atomicAdd(&g_deg[d], w);
}

// ---------------- fused scan (lookback) + norm ----------------
// All 391 blocks (100K threads) are co-resident in wave 1 on GB300
// (148 SMs x 2048 threads), so spinning on lower-block aggregates is safe.
__global__ __launch_bounds__(256) void scan_fused_kernel() {
    int tid = threadIdx.x, b = blockIdx.x;
    int i = b * 256 + tid;
    int v = (i < N_NODES) ? g_cnt[i] : 0;

    // block aggregate
    __shared__ int rd[256];
    rd[tid] = v;
    __syncthreads();
    for (int o = 128; o > 0; o >>= 1) {
        if (tid < o) rd[tid] += rd[tid + o];
        __syncthreads();
    }
    if (tid == 0) atomicExch(&g_agg[b], rd[0] | AGG_FLAG);

    // lookback: sum aggregates of all lower blocks
    int acc = 0;
    for (int j = tid; j < b; j += 256) {
        int a;
        do { a = ((volatile int*)g_agg)[j]; } while (!(a & AGG_FLAG));
        acc += a & (AGG_FLAG - 1);
    }
    __syncthreads();
    rd[tid] = acc;
    __syncthreads();
    for (int o = 128; o > 0; o >>= 1) {
        if (tid < o) rd[tid] += rd[tid + o];
        __syncthreads();
    }
    int block_off = rd[0];

    // intra-block exclusive scan of v
    unsigned lane = tid & 31, wid = tid >> 5;
    int x = v;
    for (int o = 1; o < 32; o <<= 1) {
        int y = __shfl_up_sync(0xffffffffu, x, o);
        if (lane >= o) x += y;
    }
    __shared__ int ws[8];
    if (lane == 31) ws[wid] = x;
    __syncthreads();
    if (wid == 0) {
        int s = (lane < 8) ? ws[lane] : 0;
        for (int o = 1; o < 8; o <<= 1) {
            int y = __shfl_up_sync(0xffffffffu, s, o);
            if (lane >= o) s += y;
        }
        if (lane < 8) ws[lane] = s;
    }
    __syncthreads();
    int excl = x - v + (wid ? ws[wid - 1] : 0) + block_off;
    if (i < N_NODES) {
        g_row[i] = excl;
        g_cur[i] = excl;
        g_norm[i] = rsqrtf(fmaxf(g_deg[i], 1.0f));
    }
}

// ---------------- scatter: build perm (src sorted by dst) ----------------
__global__ void scatter_kernel(const int* __restrict__ src,
                               const int* __restrict__ dst) {
    int e = blockIdx.x * blockDim.x + threadIdx.x;
    if (e >= N_EDGES) return;
    int p = atomicAdd(&g_cur[dst[e]], 1);
    g_perm[p] = src[e];
}

// ---------------- gather pass 1: S1n = norm * A*(norm*feats) ----------------
// 16 threads/node; norm[s] loads are warp-broadcast (all 16 lanes same addr).
__global__ __launch_bounds__(256) void gather1_kernel(const float* __restrict__ feats) {
    int t = blockIdx.x * 256 + threadIdx.x;
    int n = t >> 4, c = t & 15;
    int e = g_row[n];
    int eend = e + g_cnt[n];
    float4 acc = make_float4(0.f, 0.f, 0.f, 0.f);
    const float4* F = (const float4*)feats;
    for (; e + 3 < eend; e += 4) {
        int s0 = g_perm[e], s1 = g_perm[e + 1];
        int s2 = g_perm[e + 2], s3 = g_perm[e + 3];
        float n0 = g_norm[s0], n1 = g_norm[s1];
        float n2 = g_norm[s2], n3 = g_norm[s3];
        float4 a = F[s0 * 16 + c];
        float4 b = F[s1 * 16 + c];
        float4 cc = F[s2 * 16 + c];
        float4 dd = F[s3 * 16 + c];
        acc.x = fmaf(n0, a.x, fmaf(n1, b.x, fmaf(n2, cc.x, fmaf(n3, dd.x, acc.x))));
        acc.y = fmaf(n0, a.y, fmaf(n1, b.y, fmaf(n2, cc.y, fmaf(n3, dd.y, acc.y))));
        acc.z = fmaf(n0, a.z, fmaf(n1, b.z, fmaf(n2, cc.z, fmaf(n3, dd.z, acc.z))));
        acc.w = fmaf(n0, a.w, fmaf(n1, b.w, fmaf(n2, cc.w, fmaf(n3, dd.w, acc.w))));
    }
    for (; e < eend; e++) {
        int s0 = g_perm[e];
        float n0 = g_norm[s0];
        float4 a = F[s0 * 16 + c];
        acc.x = fmaf(n0, a.x, acc.x);
        acc.y = fmaf(n0, a.y, acc.y);
        acc.z = fmaf(n0, a.z, acc.z);
        acc.w = fmaf(n0, a.w, acc.w);
    }
    float nm = g_norm[n];
    ((float4*)g_S1n)[n * 16 + c] =
        make_float4(acc.x * nm, acc.y * nm, acc.z * nm, acc.w * nm);
}

// ---------------- gather pass 2: S2n = norm * A*(norm*S1n) ----------------
__global__ __launch_bounds__(256) void gather2_kernel() {
    int t = blockIdx.x * 256 + threadIdx.x;
    int n = t >> 4, c = t & 15;
    int e = g_row[n];
    int eend = e + g_cnt[n];
    float4 acc = make_float4(0.f, 0.f, 0.f, 0.f);
    const float4* F = (const float4*)g_S1n;
    for (; e + 3 < eend; e += 4) {
        int s0 = g_perm[e], s1 = g_perm[e + 1];
        int s2 = g_perm[e + 2], s3 = g_perm[e + 3];
        float n0 = g_norm[s0], n1 = g_norm[s1];
        float n2 = g_norm[s2], n3 = g_norm[s3];
        float4 a = F[s0 * 16 + c];
        float4 b = F[s1 * 16 + c];
        float4 cc = F[s2 * 16 + c];
        float4 dd = F[s3 * 16 + c];
        acc.x = fmaf(n0, a.x, fmaf(n1, b.x, fmaf(n2, cc.x, fmaf(n3, dd.x, acc.x))));
        acc.y = fmaf(n0, a.y, fmaf(n1, b.y, fmaf(n2, cc.y, fmaf(n3, dd.y, acc.y))));
        acc.z = fmaf(n0, a.z, fmaf(n1, b.z, fmaf(n2, cc.z, fmaf(n3, dd.z, acc.z))));
        acc.w = fmaf(n0, a.w, fmaf(n1, b.w, fmaf(n2, cc.w, fmaf(n3, dd.w, acc.w))));
    }
    for (; e < eend; e++) {
        int s0 = g_perm[e];
        float n0 = g_norm[s0];
        float4 a = F[s0 * 16 + c];
        acc.x = fmaf(n0, a.x, acc.x);
        acc.y = fmaf(n0, a.y, acc.y);
        acc.z = fmaf(n0, a.z, acc.z);
        acc.w = fmaf(n0, a.w, acc.w);
    }
    float nm = g_norm[n];
    ((float4*)g_S2n)[n * 16 + c] =
        make_float4(acc.x * nm, acc.y * nm, acc.z * nm, acc.w * nm);
}

// ================= HMMA (mma.sync) GEMM with bf16 hi/lo split =============
__device__ __forceinline__ void mma16816(float* c, const uint32_t* a,
                                         uint32_t b0, uint32_t b1) {
    asm volatile(
        "mma.sync.aligned.m16n8k16.row.col.f32.bf16.bf16.f32 "
        "{%0,%1,%2,%3}, {%4,%5,%6,%7}, {%8,%9}, {%0,%1,%2,%3};"
        : "+f"(c[0]), "+f"(c[1]), "+f"(c[2]), "+f"(c[3])
        : "r"(a[0]), "r"(a[1]), "r"(a[2]), "r"(a[3]), "r"(b0), "r"(b1));
}

__device__ __forceinline__ uint32_t pack_bf16(float a, float b) {
    __nv_bfloat162 t = __floats2bfloat162_rn(a, b);
    return *reinterpret_cast<uint32_t*>(&t);
}

#define ASTRIDE 33   // words per row (66 bf16)

// m selects the A operand IN DEVICE CODE (device symbols aren't host pointers).
__global__ __launch_bounds__(64) void gemm_tc_kernel(
    const float* __restrict__ feats,
    const float* __restrict__ W,
    float* __restrict__ out, int m) {
    __shared__ __align__(16) uint32_t sAhi[64 * ASTRIDE];
    __shared__ __align__(16) uint32_t sAlo[64 * ASTRIDE];
    __shared__ __align__(16) uint32_t sBhi[64 * ASTRIDE];   // Wt[n][k]
    __shared__ __align__(16) uint32_t sBlo[64 * ASTRIDE];

    int tid = threadIdx.x;
    int w = tid >> 5, lane = tid & 31;
    int g = lane >> 2, q = lane & 3;
    int rowbase = blockIdx.x * 64;

    const float* A = (m == 0) ? feats : (m == 1) ? g_S1n : g_S2n;

    // ---- stage A: one row per thread, f32 -> bf16 hi/lo
    {
        int grow = rowbase + tid;
        if (grow < N_NODES) {
            const float4* rp = (const float4*)(A + (size_t)grow * 64);
#pragma unroll
            for (int i = 0; i < 16; i++) {
                float4 v = rp[i];
                float h0 = __bfloat162float(__float2bfloat16_rn(v.x));
                float h1 = __bfloat162float(__float2bfloat16_rn(v.y));
                float h2 = __bfloat162float(__float2bfloat16_rn(v.z));
                float h3 = __bfloat162float(__float2bfloat16_rn(v.w));
                sAhi[tid * ASTRIDE + 2 * i + 0] = pack_bf16(h0, h1);
                sAhi[tid * ASTRIDE + 2 * i + 1] = pack_bf16(h2, h3);
                sAlo[tid * ASTRIDE + 2 * i + 0] = pack_bf16(v.x - h0, v.y - h1);
                sAlo[tid * ASTRIDE + 2 * i + 1] = pack_bf16(v.z - h2, v.w - h3);
            }
        } else {
#pragma unroll
            for (int i = 0; i < 32; i++) {
                sAhi[tid * ASTRIDE + i] = 0;
                sAlo[tid * ASTRIDE + i] = 0;
            }
        }
    }

    // ---- stage B: Wt[n][k] bf16 hi/lo (W is [k][n] row-major f32)
    {
        __nv_bfloat16* bh = (__nv_bfloat16*)sBhi;
        __nv_bfloat16* bl = (__nv_bfloat16*)sBlo;
#pragma unroll
        for (int i = 0; i < 64; i++) {
            int idx = tid + i * 64;          // idx = k*64 + n
            float v = W[idx];
            int k = idx >> 6, n = idx & 63;
            float h = __bfloat162float(__float2bfloat16_rn(v));
            bh[n * 66 + k] = __float2bfloat16_rn(v);
            bl[n * 66 + k] = __float2bfloat16_rn(v - h);
        }
    }
    __syncthreads();

    // ---- MMA mainloop
    float acc[2][8][4];
#pragma unroll
    for (int mt = 0; mt < 2; mt++)
#pragma unroll
        for (int nt = 0; nt < 8; nt++)
#pragma unroll
            for (int i = 0; i < 4; i++) acc[mt][nt][i] = 0.f;

#pragma unroll
    for (int ks = 0; ks < 4; ks++) {
        uint32_t bh[8][2], bl[8][2];
#pragma unroll
        for (int nt = 0; nt < 8; nt++) {
            int n = nt * 8 + g;
            int bw = n * ASTRIDE + q + ks * 8;
            bh[nt][0] = sBhi[bw];     bh[nt][1] = sBhi[bw + 4];
            bl[nt][0] = sBlo[bw];     bl[nt][1] = sBlo[bw + 4];
        }
#pragma unroll
        for (int mt = 0; mt < 2; mt++) {
            int r0 = w * 32 + mt * 16 + g;
            int aw0 = r0 * ASTRIDE + q + ks * 8;
            int aw1 = (r0 + 8) * ASTRIDE + q + ks * 8;
            uint32_t ahi[4] = {sAhi[aw0], sAhi[aw1], sAhi[aw0 + 4], sAhi[aw1 + 4]};
            uint32_t alo[4] = {sAlo[aw0], sAlo[aw1], sAlo[aw0 + 4], sAlo[aw1 + 4]};
#pragma unroll
            for (int nt = 0; nt < 8; nt++) {
                mma16816(acc[mt][nt], ahi, bh[nt][0], bh[nt][1]);
                mma16816(acc[mt][nt], ahi, bl[nt][0], bl[nt][1]);
                mma16816(acc[mt][nt], alo, bh[nt][0], bh[nt][1]);
            }
        }
    }

    // ---- epilogue
#pragma unroll
    for (int mt = 0; mt < 2; mt++) {
        int r0 = rowbase + w * 32 + mt * 16 + g;
#pragma unroll
        for (int nt = 0; nt < 8; nt++) {
            int col = m * 64 + nt * 8 + q * 2;
            if (r0 < N_NODES)
                *(float2*)(out + (size_t)r0 * 192 + col) =
                    make_float2(acc[mt][nt][0], acc[mt][nt][1]);
            if (r0 + 8 < N_NODES)
                *(float2*)(out + (size_t)(r0 + 8) * 192 + col) =
                    make_float2(acc[mt][nt][2], acc[mt][nt][3]);
        }
    }
}

// =================== launch ===================
extern "C" void kernel_launch(void* const* d_in, const int* in_sizes, int n_in,
                              void* d_out, int out_size) {
    const float* feats       = (const float*)d_in[0];
    const float* edge_weight = (const float*)d_in[1];
    const float* w0          = (const float*)d_in[2];
    const float* w1          = (const float*)d_in[3];
    const float* w2          = (const float*)d_in[4];
    const int*   src         = (const int*)d_in[5];
    const int*   dst         = (const int*)d_in[6];
    const int*   e_feat      = (const int*)d_in[7];
    float* out = (float*)d_out;

    // Created once on the first (eager, uncaptured) correctness call.
    static cudaStream_t s1 = nullptr, s2 = nullptr;
    static cudaEvent_t eStart, eG1, eM0, eM1;
    if (!s1) {
        cudaStreamCreateWithFlags(&s1, cudaStreamNonBlocking);
        cudaStreamCreateWithFlags(&s2, cudaStreamNonBlocking);
        cudaEventCreateWithFlags(&eStart, cudaEventDisableTiming);
        cudaEventCreateWithFlags(&eG1, cudaEventDisableTiming);
        cudaEventCreateWithFlags(&eM0, cudaEventDisableTiming);
        cudaEventCreateWithFlags(&eM1, cudaEventDisableTiming);
    }

    // fork point at t=0: gemm m=0 depends only on feats
    cudaEventRecord(eStart, 0);
    cudaStreamWaitEvent(s2, eStart, 0);
    gemm_tc_kernel<<<GTILES, 64, 0, s2>>>(feats, w0, out, 0);
    cudaEventRecord(eM0, s2);

    // main pipeline
    zero_kernel<<<(50432) / 256, 256>>>();
    hist_kernel<<<(N_EDGES + 255) / 256, 256>>>(dst, e_feat, edge_weight);
    scan_fused_kernel<<<NBLK_SCAN, 256>>>();
    scatter_kernel<<<(N_EDGES + 255) / 256, 256>>>(src, dst);
    gather1_kernel<<<(N_NODES * 16) / 256, 256>>>(feats);
    cudaEventRecord(eG1, 0);

    // s1: gemm m=1 overlaps gather2
    cudaStreamWaitEvent(s1, eG1, 0);
    gemm_tc_kernel<<<GTILES, 64, 0, s1>>>(feats, w1, out, 1);
    cudaEventRecord(eM1, s1);

    // main: gather2 + gemm m=2
    gather2_kernel<<<(N_NODES * 16) / 256, 256>>>();
    gemm_tc_kernel<<<GTILES, 64>>>(feats, w2, out, 2);

    // join
    cudaStreamWaitEvent(0, eM0, 0);
    cudaStreamWaitEvent(0, eM1, 0);
}

// round 8
// speedup vs baseline: 1.0375x; 1.0067x over previous
#include <cuda_runtime.h>
#include <cuda_bf16.h>
#include <cstdint>

#define N_NODES 100000
#define N_EDGES 1000000
#define D 64
#define ALPHA 10.0f
#define NBLK_SCAN 391    // ceil(100000/256)
#define GTILES 1563      // ceil(100000/64)
#define AGG_FLAG 0x40000000

// ---------------- scratch (device globals; zero-init at module load) ------
__device__ int   g_cnt[N_NODES];           // self-cleaned by scan
__device__ int   g_row[N_NODES + 1];       // CSR prefix (N+1 entries)
__device__ int   g_cur[N_NODES];
__device__ int   g_agg[NBLK_SCAN];         // self-cleaned by scatter
__device__ int   g_perm[N_EDGES];          // src ids, sorted by dst
__device__ float g_deg[N_NODES];           // self-cleaned by scan
__device__ float g_norm[N_NODES];
__device__ float g_S1n[N_NODES * D];       // norm * S1
__device__ float g_S2n[N_NODES * D];       // norm * S2

// ---------------- histogram + weighted degree ----------------
__global__ void hist_kernel(const int* __restrict__ dst,
                            const int* __restrict__ e_feat,
                            const float* __restrict__ edge_weight) {
    int e = blockIdx.x * blockDim.x + threadIdx.x;
    if (e >= N_EDGES) return;
    int d = dst[e];
    atomicAdd(&g_cnt[d], 1);
    float x = edge_weight[e_feat[e] - 1] * ALPHA;
    float w = x > 0.f ? x : 0.01f * x;   // leaky_relu
    atomicAdd(&g_deg[d], w);
}

// ---------------- fused scan (lookback) + norm + self-clean ----------------
// All 391 blocks are co-resident in wave 1, so spinning is deadlock-free.
__global__ __launch_bounds__(256) void scan_fused_kernel() {
    int tid = threadIdx.x, b = blockIdx.x;
    int i = b * 256 + tid;
    int v = (i < N_NODES) ? g_cnt[i] : 0;

    // block aggregate
    __shared__ int rd[256];
    rd[tid] = v;
    __syncthreads();
    for (int o = 128; o > 0; o >>= 1) {
        if (tid < o) rd[tid] += rd[tid + o];
        __syncthreads();
    }
    if (tid == 0) atomicExch(&g_agg[b], rd[0] | AGG_FLAG);

    // lookback: sum aggregates of all lower blocks
    int acc = 0;
    for (int j = tid; j < b; j += 256) {
        int a;
        do { a = ((volatile int*)g_agg)[j]; } while (!(a & AGG_FLAG));
        acc += a & (AGG_FLAG - 1);
    }
    __syncthreads();
    rd[tid] = acc;
    __syncthreads();
    for (int o = 128; o > 0; o >>= 1) {
        if (tid < o) rd[tid] += rd[tid + o];
        __syncthreads();
    }
    int block_off = rd[0];

    // intra-block exclusive scan of v
    unsigned lane = tid & 31, wid = tid >> 5;
    int x = v;
    for (int o = 1; o < 32; o <<= 1) {
        int y = __shfl_up_sync(0xffffffffu, x, o);
        if (lane >= o) x += y;
    }
    __shared__ int ws[8];
    if (lane == 31) ws[wid] = x;
    __syncthreads();
    if (wid == 0) {
        int s = (lane < 8) ? ws[lane] : 0;
        for (int o = 1; o < 8; o <<= 1) {
            int y = __shfl_up_sync(0xffffffffu, s, o);
            if (lane >= o) s += y;
        }
        if (lane < 8) ws[lane] = s;
    }
    __syncthreads();
    int excl = x - v + (wid ? ws[wid - 1] : 0) + block_off;
    if (i < N_NODES) {
        g_row[i] = excl;
        g_cur[i] = excl;
        g_norm[i] = rsqrtf(fmaxf(g_deg[i], 1.0f));
        g_cnt[i] = 0;          // self-clean for next replay
        g_deg[i] = 0.f;        // self-clean for next replay
        if (i == N_NODES - 1) g_row[N_NODES] = excl + v;
    }
}

// ---------------- scatter: build perm; also self-clean agg ----------------
__global__ void scatter_kernel(const int* __restrict__ src,
                               const int* __restrict__ dst) {
    int e = blockIdx.x * blockDim.x + threadIdx.x;
    if (e < NBLK_SCAN) g_agg[e] = 0;    // reset lookback flags for next replay
    if (e >= N_EDGES) return;
    int p = atomicAdd(&g_cur[dst[e]], 1);
    g_perm[p] = src[e];
}

// ---------------- gather pass 1: S1n = norm * A*(norm*feats) ----------------
__global__ __launch_bounds__(256) void gather1_kernel(const float* __restrict__ feats) {
    int t = blockIdx.x * 256 + threadIdx.x;
    int n = t >> 4, c = t & 15;
    int e = g_row[n];
    int eend = g_row[n + 1];
    float4 acc = make_float4(0.f, 0.f, 0.f, 0.f);
    const float4* F = (const float4*)feats;
    for (; e + 3 < eend; e += 4) {
        int s0 = g_perm[e], s1 = g_perm[e + 1];
        int s2 = g_perm[e + 2], s3 = g_perm[e + 3];
        float n0 = g_norm[s0], n1 = g_norm[s1];
        float n2 = g_norm[s2], n3 = g_norm[s3];
        float4 a = F[s0 * 16 + c];
        float4 b = F[s1 * 16 + c];
        float4 cc = F[s2 * 16 + c];
        float4 dd = F[s3 * 16 + c];
        acc.x = fmaf(n0, a.x, fmaf(n1, b.x, fmaf(n2, cc.x, fmaf(n3, dd.x, acc.x))));
        acc.y = fmaf(n0, a.y, fmaf(n1, b.y, fmaf(n2, cc.y, fmaf(n3, dd.y, acc.y))));
        acc.z = fmaf(n0, a.z, fmaf(n1, b.z, fmaf(n2, cc.z, fmaf(n3, dd.z, acc.z))));
        acc.w = fmaf(n0, a.w, fmaf(n1, b.w, fmaf(n2, cc.w, fmaf(n3, dd.w, acc.w))));
    }
    for (; e < eend; e++) {
        int s0 = g_perm[e];
        float n0 = g_norm[s0];
        float4 a = F[s0 * 16 + c];
        acc.x = fmaf(n0, a.x, acc.x);
        acc.y = fmaf(n0, a.y, acc.y);
        acc.z = fmaf(n0, a.z, acc.z);
        acc.w = fmaf(n0, a.w, acc.w);
    }
    float nm = g_norm[n];
    ((float4*)g_S1n)[n * 16 + c] =
        make_float4(acc.x * nm, acc.y * nm, acc.z * nm, acc.w * nm);
}

// ---------------- gather pass 2: S2n = norm * A*(norm*S1n) ----------------
__global__ __launch_bounds__(256) void gather2_kernel() {
    int t = blockIdx.x * 256 + threadIdx.x;
    int n = t >> 4, c = t & 15;
    int e = g_row[n];
    int eend = g_row[n + 1];
    float4 acc = make_float4(0.f, 0.f, 0.f, 0.f);
    const float4* F = (const float4*)g_S1n;
    for (; e + 3 < eend; e += 4) {
        int s0 = g_perm[e], s1 = g_perm[e + 1];
        int s2 = g_perm[e + 2], s3 = g_perm[e + 3];
        float n0 = g_norm[s0], n1 = g_norm[s1];
        float n2 = g_norm[s2], n3 = g_norm[s3];
        float4 a = F[s0 * 16 + c];
        float4 b = F[s1 * 16 + c];
        float4 cc = F[s2 * 16 + c];
        float4 dd = F[s3 * 16 + c];
        acc.x = fmaf(n0, a.x, fmaf(n1, b.x, fmaf(n2, cc.x, fmaf(n3, dd.x, acc.x))));
        acc.y = fmaf(n0, a.y, fmaf(n1, b.y, fmaf(n2, cc.y, fmaf(n3, dd.y, acc.y))));
        acc.z = fmaf(n0, a.z, fmaf(n1, b.z, fmaf(n2, cc.z, fmaf(n3, dd.z, acc.z))));
        acc.w = fmaf(n0, a.w, fmaf(n1, b.w, fmaf(n2, cc.w, fmaf(n3, dd.w, acc.w))));
    }
    for (; e < eend; e++) {
        int s0 = g_perm[e];
        float n0 = g_norm[s0];
        float4 a = F[s0 * 16 + c];
        acc.x = fmaf(n0, a.x, acc.x);
        acc.y = fmaf(n0, a.y, acc.y);
        acc.z = fmaf(n0, a.z, acc.z);
        acc.w = fmaf(n0, a.w, acc.w);
    }
    float nm = g_norm[n];
    ((float4*)g_S2n)[n * 16 + c] =
        make_float4(acc.x * nm, acc.y * nm, acc.z * nm, acc.w * nm);
}

// ================= HMMA (mma.sync) GEMM with fast bf16 hi/lo split =========
__device__ __forceinline__ void mma16816(float* c, const uint32_t* a,
                                         uint32_t b0, uint32_t b1) {
    asm volatile(
        "mma.sync.aligned.m16n8k16.row.col.f32.bf16.bf16.f32 "
        "{%0,%1,%2,%3}, {%4,%5,%6,%7}, {%8,%9}, {%0,%1,%2,%3};"
        : "+f"(c[0]), "+f"(c[1]), "+f"(c[2]), "+f"(c[3])
        : "r"(a[0]), "r"(a[1]), "r"(a[2]), "r"(a[3]), "r"(b0), "r"(b1));
}

// pack two floats into bf16x2 with rn rounding: lo -> bits[15:0], hi -> bits[31:16]
__device__ __forceinline__ uint32_t pack2_bf16(float lo, float hi) {
    uint32_t r;
    asm("cvt.rn.bf16x2.f32 %0, %1, %2;" : "=r"(r) : "f"(hi), "f"(lo));
    return r;
}

#define ASTRIDE 33   // words per row (66 bf16)

// m selects the A operand IN DEVICE CODE (device symbols aren't host pointers).
__global__ __launch_bounds__(64) void gemm_tc_kernel(
    const float* __restrict__ feats,
    const float* __restrict__ W,
    float* __restrict__ out, int m) {
    __shared__ __align__(16) uint32_t sAhi[64 * ASTRIDE];
    __shared__ __align__(16) uint32_t sAlo[64 * ASTRIDE];
    __shared__ __align__(16) uint32_t sBhi[64 * ASTRIDE];   // Wt[n][k]
    __shared__ __align__(16) uint32_t sBlo[64 * ASTRIDE];

    int tid = threadIdx.x;
    int w = tid >> 5, lane = tid & 31;
    int g = lane >> 2, q = lane & 3;
    int rowbase = blockIdx.x * 64;

    const float* A = (m == 0) ? feats : (m == 1) ? g_S1n : g_S2n;

    // ---- stage A: one row per thread, truncation hi-split + bf16 lo
    {
        int grow = rowbase + tid;
        if (grow < N_NODES) {
            const float4* rp = (const float4*)(A + (size_t)grow * 64);
#pragma unroll
            for (int i = 0; i < 16; i++) {
                float4 v = rp[i];
                uint32_t bx = __float_as_uint(v.x) & 0xFFFF0000u;
                uint32_t by = __float_as_uint(v.y) & 0xFFFF0000u;
                uint32_t bz = __float_as_uint(v.z) & 0xFFFF0000u;
                uint32_t bw = __float_as_uint(v.w) & 0xFFFF0000u;
                sAhi[tid * ASTRIDE + 2 * i + 0] = __byte_perm(bx, by, 0x7632);
                sAhi[tid * ASTRIDE + 2 * i + 1] = __byte_perm(bz, bw, 0x7632);
                sAlo[tid * ASTRIDE + 2 * i + 0] =
                    pack2_bf16(v.x - __uint_as_float(bx), v.y - __uint_as_float(by));
                sAlo[tid * ASTRIDE + 2 * i + 1] =
                    pack2_bf16(v.z - __uint_as_float(bz), v.w - __uint_as_float(bw));
            }
        } else {
#pragma unroll
            for (int i = 0; i < 32; i++) {
                sAhi[tid * ASTRIDE + i] = 0;
                sAlo[tid * ASTRIDE + i] = 0;
            }
        }
    }

    // ---- stage B: Wt[n][k] hi/lo (W is [k][n] row-major f32)
    {
        uint16_t* bh = (uint16_t*)sBhi;
        __nv_bfloat16* bl = (__nv_bfloat16*)sBlo;
#pragma unroll
        for (int i = 0; i < 64; i++) {
            int idx = tid + i * 64;          // idx = k*64 + n
            float v = W[idx];
            int k = idx >> 6, n = idx & 63;
            uint32_t b = __float_as_uint(v) & 0xFFFF0000u;
            bh[n * 66 + k] = (uint16_t)(b >> 16);
            bl[n * 66 + k] = __float2bfloat16_rn(v - __uint_as_float(b));
        }
    }
    __syncthreads();

    // ---- MMA mainloop
    float acc[2][8][4];
#pragma unroll
    for (int mt = 0; mt < 2; mt++)
#pragma unroll
        for (int nt = 0; nt < 8; nt++)
#pragma unroll
            for (int i = 0; i < 4; i++) acc[mt][nt][i] = 0.f;

#pragma unroll
    for (int ks = 0; ks < 4; ks++) {
        uint32_t bh[8][2], bl[8][2];
#pragma unroll
        for (int nt = 0; nt < 8; nt++) {
            int n = nt * 8 + g;
            int bw = n * ASTRIDE + q + ks * 8;
            bh[nt][0] = sBhi[bw];     bh[nt][1] = sBhi[bw + 4];
            bl[nt][0] = sBlo[bw];     bl[nt][1] = sBlo[bw + 4];
        }
#pragma unroll
        for (int mt = 0; mt < 2; mt++) {
            int r0 = w * 32 + mt * 16 + g;
            int aw0 = r0 * ASTRIDE + q + ks * 8;
            int aw1 = (r0 + 8) * ASTRIDE + q + ks * 8;
            uint32_t ahi[4] = {sAhi[aw0], sAhi[aw1], sAhi[aw0 + 4], sAhi[aw1 + 4]};
            uint32_t alo[4] = {sAlo[aw0], sAlo[aw1], sAlo[aw0 + 4], sAlo[aw1 + 4]};
#pragma unroll
            for (int nt = 0; nt < 8; nt++) {
                mma16816(acc[mt][nt], ahi, bh[nt][0], bh[nt][1]);
                mma16816(acc[mt][nt], ahi, bl[nt][0], bl[nt][1]);
                mma16816(acc[mt][nt], alo, bh[nt][0], bh[nt][1]);
            }
        }
    }

    // ---- epilogue
#pragma unroll
    for (int mt = 0; mt < 2; mt++) {
        int r0 = rowbase + w * 32 + mt * 16 + g;
#pragma unroll
        for (int nt = 0; nt < 8; nt++) {
            int col = m * 64 + nt * 8 + q * 2;
            if (r0 < N_NODES)
                *(float2*)(out + (size_t)r0 * 192 + col) =
                    make_float2(acc[mt][nt][0], acc[mt][nt][1]);
            if (r0 + 8 < N_NODES)
                *(float2*)(out + (size_t)(r0 + 8) * 192 + col) =
                    make_float2(acc[mt][nt][2], acc[mt][nt][3]);
        }
    }
}

// =================== launch ===================
extern "C" void kernel_launch(void* const* d_in, const int* in_sizes, int n_in,
                              void* d_out, int out_size) {
    const float* feats       = (const float*)d_in[0];
    const float* edge_weight = (const float*)d_in[1];
    const float* w0          = (const float*)d_in[2];
    const float* w1          = (const float*)d_in[3];
    const float* w2          = (const float*)d_in[4];
    const int*   src         = (const int*)d_in[5];
    const int*   dst         = (const int*)d_in[6];
    const int*   e_feat      = (const int*)d_in[7];
    float* out = (float*)d_out;

    static cudaStream_t s1 = nullptr, s2 = nullptr;
    static cudaEvent_t eStart, eG1, eM0, eM1;
    if (!s1) {
        cudaStreamCreateWithFlags(&s1, cudaStreamNonBlocking);
        cudaStreamCreateWithFlags(&s2, cudaStreamNonBlocking);
        cudaEventCreateWithFlags(&eStart, cudaEventDisableTiming);
        cudaEventCreateWithFlags(&eG1, cudaEventDisableTiming);
        cudaEventCreateWithFlags(&eM0, cudaEventDisableTiming);
        cudaEventCreateWithFlags(&eM1, cudaEventDisableTiming);
    }

    // fork at t=0: gemm m=0 depends only on feats
    cudaEventRecord(eStart, 0);
    cudaStreamWaitEvent(s2, eStart, 0);
    gemm_tc_kernel<<<GTILES, 64, 0, s2>>>(feats, w0, out, 0);
    cudaEventRecord(eM0, s2);

    // main pipeline (self-cleaning; no zero kernel)
    hist_kernel<<<(N_EDGES + 255) / 256, 256>>>(dst, e_feat, edge_weight);
    scan_fused_kernel<<<NBLK_SCAN, 256>>>();
    scatter_kernel<<<(N_EDGES + 255) / 256, 256>>>(src, dst);
    gather1_kernel<<<(N_NODES * 16) / 256, 256>>>(feats);
    cudaEventRecord(eG1, 0);

    // s1: gemm m=1 overlaps gather2
    cudaStreamWaitEvent(s1, eG1, 0);
    gemm_tc_kernel<<<GTILES, 64, 0, s1>>>(feats, w1, out, 1);
    cudaEventRecord(eM1, s1);

    // main: gather2 + gemm m=2
    gather2_kernel<<<(N_NODES * 16) / 256, 256>>>();
    gemm_tc_kernel<<<GTILES, 64>>>(feats, w2, out, 2);

    // join
    cudaStreamWaitEvent(0, eM0, 0);
    cudaStreamWaitEvent(0, eM1, 0);
}